// round 12
// baseline (speedup 1.0000x reference)
#include <cuda_runtime.h>
#include <cuda_bf16.h>
#include <cstdint>

#define C_DIM 2048
#define R_DIM 1024
#define B_DIM 16

#define ROWS_PER_BLOCK 16
#define CHUNK_ROWS 2
#define NCHUNKS (ROWS_PER_BLOCK / CHUNK_ROWS)      /* 8 */
#define NBUF 4
#define CHUNK_BYTES (CHUNK_ROWS * C_DIM * 4)       /* 16384 */
#define SMEM_TOTAL (NBUF * CHUNK_BYTES + 128)      /* 4 buffers + mbarrier pairs */

// Device-global scratch (no allocations allowed)
__device__ int g_sel_b[C_DIM];   // out col j reads input col g_sel_b[j]
__device__ int g_inv_r[R_DIM];   // input row q goes to output row g_inv_r[q]
__device__ int g_flag[2];        // prep-done flags (col, row); idempotent 0->1

// ---------------- PTX helpers ----------------
__device__ __forceinline__ uint32_t smem_u32(const void* p) {
    return (uint32_t)__cvta_generic_to_shared(p);
}
__device__ __forceinline__ void mbar_init(uint32_t a, uint32_t cnt) {
    asm volatile("mbarrier.init.shared.b64 [%0], %1;" :: "r"(a), "r"(cnt) : "memory");
}
__device__ __forceinline__ void mbar_expect_tx(uint32_t a, uint32_t bytes) {
    asm volatile("mbarrier.arrive.expect_tx.shared.b64 _, [%0], %1;"
                 :: "r"(a), "r"(bytes) : "memory");
}
__device__ __forceinline__ void mbar_arrive(uint32_t a) {
    asm volatile("mbarrier.arrive.shared.b64 _, [%0];" :: "r"(a) : "memory");
}
__device__ __forceinline__ void mbar_wait(uint32_t a, uint32_t parity) {
    asm volatile(
        "{\n\t.reg .pred P;\n\t"
        "WAIT_%=:\n\t"
        "mbarrier.try_wait.parity.acquire.cta.shared::cta.b64 P, [%0], %1, 0x989680;\n\t"
        "@P bra.uni DONE_%=;\n\t"
        "bra.uni WAIT_%=;\n\t"
        "DONE_%=:\n\t}"
        :: "r"(a), "r"(parity) : "memory");
}
__device__ __forceinline__ void bulk_ld(uint32_t dst, const void* src,
                                        uint32_t bytes, uint32_t mbar) {
    asm volatile(
        "cp.async.bulk.shared::cluster.global.mbarrier::complete_tx::bytes [%0], [%1], %2, [%3];"
        :: "r"(dst), "l"(src), "r"(bytes), "r"(mbar) : "memory");
}

// ---------------- block-wide inclusive scan (1024 threads) ----------------
__device__ __forceinline__ void block_scan(int* a, int n, int tid, int* wsum) {
    const int lane = tid & 31, wid = tid >> 5;
    int v0 = 0, v1 = 0;
    const int i0 = 2 * tid;
    if (n == 2048) { v0 = a[i0]; v1 = a[i0 + 1]; }
    else           { v0 = a[tid]; }
    int s = v0 + v1;
    #pragma unroll
    for (int off = 1; off < 32; off <<= 1) {
        int y = __shfl_up_sync(0xffffffffu, s, off);
        if (lane >= off) s += y;
    }
    if (lane == 31) wsum[wid] = s;
    __syncthreads();
    if (wid == 0) {
        int t = wsum[lane];
        #pragma unroll
        for (int off = 1; off < 32; off <<= 1) {
            int y = __shfl_up_sync(0xffffffffu, t, off);
            if (lane >= off) t += y;
        }
        wsum[lane] = t;
    }
    __syncthreads();
    const int excl = (wid ? wsum[wid - 1] : 0) + s - (v0 + v1);
    if (n == 2048) { a[i0] = excl + v0; a[i0 + 1] = excl + v0 + v1; }
    else           { a[tid] = excl + v0; }
    __syncthreads();
}

// ---------------------------------------------------------------------------
// Fused kernel. Blocks 0,1: prep (dedup indices). Blocks 2..: 16 input rows
// each, 4-deep TMA ring with full/empty mbarrier pairs — NO __syncthreads in
// the consume loop; warps drift up to NBUF chunks; tid0 reissues loads as
// soon as the slowest consumer releases a buffer.
// ---------------------------------------------------------------------------
__global__ void __launch_bounds__(1024, 2)
fused_kernel(const float* __restrict__ x, const float* __restrict__ wc,
             const float* __restrict__ wr, float* __restrict__ out)
{
    extern __shared__ char smem[];
    const int tid = threadIdx.x;

    if (blockIdx.x < 2) {
        // ================= PREP =================
        const bool  isC = (blockIdx.x == 0);
        const int   n   = isC ? C_DIM : R_DIM;
        const float* w  = isC ? wc : wr;

        int* sel         = (int*)smem;
        int* firstIdx    = sel + C_DIM;
        int* scanA       = firstIdx + C_DIM;
        int* emptyByRank = scanA + C_DIM;
        __shared__ int wsum[32];
        __shared__ int sh_E;

        const float upper = (float)(n - 1);
        if (n == 2048) {
            const int i0 = 2 * tid;
            sel[i0]     = __float2int_rn(fminf(fmaxf(w[i0],     0.0f), upper));
            sel[i0 + 1] = __float2int_rn(fminf(fmaxf(w[i0 + 1], 0.0f), upper));
            firstIdx[i0] = 0x7fffffff; firstIdx[i0 + 1] = 0x7fffffff;
        } else {
            sel[tid] = __float2int_rn(fminf(fmaxf(w[tid], 0.0f), upper));
            firstIdx[tid] = 0x7fffffff;
        }
        __syncthreads();
        for (int i = tid; i < n; i += 1024) atomicMin(&firstIdx[sel[i]], i);
        __syncthreads();

        // pass 1: scan EMPTY flags over values -> emptyByRank (descending)
        for (int v = tid; v < n; v += 1024)
            scanA[v] = (firstIdx[v] == 0x7fffffff) ? 1 : 0;
        __syncthreads();
        block_scan(scanA, n, tid, wsum);
        if (tid == 0) sh_E = scanA[n - 1];
        __syncthreads();
        const int E = sh_E;
        for (int v = tid; v < n; v += 1024) {
            if (firstIdx[v] == 0x7fffffff) {
                int asc = scanA[v] - 1;
                emptyByRank[E - 1 - asc] = v;   // slot 0 = largest empty value
            }
        }
        __syncthreads();

        // pass 2: scan DUP flags over indices -> duplicate rank
        for (int i = tid; i < n; i += 1024)
            scanA[i] = (firstIdx[sel[i]] != i) ? 1 : 0;
        __syncthreads();
        block_scan(scanA, n, tid, wsum);

        for (int i = tid; i < n; i += 1024) {
            bool dup = (firstIdx[sel[i]] != i);
            int v = dup ? emptyByRank[scanA[i] - 1] : sel[i];
            if (isC) g_sel_b[i] = v;     // column gather index
            else     g_inv_r[v] = i;     // inverse row permutation (v is a perm)
        }
        __threadfence();
        __syncthreads();
        if (tid == 0) {
            int* f = &g_flag[isC ? 0 : 1];
            asm volatile("st.release.gpu.global.b32 [%0], %1;"
                         :: "l"(f), "r"(1) : "memory");
        }
        return;
    }

    // ================= GATHER / SCATTER =================
    const int q0 = (int)(blockIdx.x - 2) * ROWS_PER_BLOCK;   // first input row
    const uint32_t sbase = smem_u32(smem);
    const uint32_t mbarb = sbase + NBUF * CHUNK_BYTES;
    // layout: full[b] = mbarb + 16*b, empty[b] = mbarb + 16*b + 8

    if (tid == 0) {
        #pragma unroll
        for (int p = 0; p < NBUF; p++) {
            mbar_init(mbarb + 16 * p, 1);         // full: tx-based
            mbar_init(mbarb + 16 * p + 8, 1024);  // empty: all consumers
        }
        asm volatile("fence.proxy.async.shared::cta;" ::: "memory");
        // Prologue: fill the ring (64KB in flight).
        #pragma unroll
        for (int p = 0; p < NBUF; p++) {
            mbar_expect_tx(mbarb + 16 * p, CHUNK_BYTES);
            bulk_ld(sbase + p * CHUNK_BYTES,
                    x + (size_t)(q0 + p * CHUNK_ROWS) * C_DIM,
                    CHUNK_BYTES, mbarb + 16 * p);
        }
        // Wait for prep (overlapped with the loads above).
        int a, b;
        do {
            asm volatile("ld.acquire.gpu.global.b32 %0, [%1];" : "=r"(a) : "l"(&g_flag[0]));
            asm volatile("ld.acquire.gpu.global.b32 %0, [%1];" : "=r"(b) : "l"(&g_flag[1]));
        } while (!(a && b));
    }
    __syncthreads();   // barriers initialized + prep visible to all

    // Fixed per-thread slot: row k within chunk (0/1), float4 column c4.
    const int c4 = tid & 511;
    const int k  = tid >> 9;
    const int4 bj = ((const int4*)g_sel_b)[c4];    // reused across all chunks

    #pragma unroll
    for (int c = 0; c < NCHUNKS; c++) {
        const int b = c & (NBUF - 1);
        const uint32_t full_mb  = mbarb + 16 * b;
        const uint32_t empty_mb = full_mb + 8;

        // Producer: refill this buffer for chunk c (issued at iteration c,
        // covering data consumed NBUF chunks from now is wrong — refill for
        // chunk c happens here only when c >= NBUF, reusing buffer b).
        if (tid == 0 && c >= NBUF) {
            mbar_wait(empty_mb, ((c / NBUF) - 1) & 1);  // all 1024 released
            mbar_expect_tx(full_mb, CHUNK_BYTES);
            bulk_ld(sbase + b * CHUNK_BYTES,
                    x + (size_t)(q0 + c * CHUNK_ROWS) * C_DIM,
                    CHUNK_BYTES, full_mb);
        }

        mbar_wait(full_mb, (c / NBUF) & 1);
        const float* srow = (const float*)(smem + b * CHUNK_BYTES) + k * C_DIM;

        const int Q = q0 + c * CHUNK_ROWS + k;               // input row (flat)
        const int orow = (Q & ~(R_DIM - 1)) | g_inv_r[Q & (R_DIM - 1)];
        float4 v;
        v.x = srow[bj.x]; v.y = srow[bj.y]; v.z = srow[bj.z]; v.w = srow[bj.w];
        __stwt(((float4*)out) + (size_t)orow * (C_DIM / 4) + c4, v);

        if (c + NBUF < NCHUNKS) mbar_arrive(empty_mb);  // release buffer
    }
}

extern "C" void kernel_launch(void* const* d_in, const int* in_sizes, int n_in,
                              void* d_out, int out_size) {
    const float* x  = (const float*)d_in[0];   // [16, 1024, 2048] f32
    const float* wc = (const float*)d_in[1];   // [2048] f32
    const float* wr = (const float*)d_in[2];   // [1024] f32
    float* out = (float*)d_out;

    cudaFuncSetAttribute(fused_kernel,
                         cudaFuncAttributeMaxDynamicSharedMemorySize, SMEM_TOTAL);
    const int grid = 2 + (B_DIM * R_DIM) / ROWS_PER_BLOCK;   // 1026
    fused_kernel<<<grid, 1024, SMEM_TOTAL>>>(x, wc, wr, out);
}

// round 14
// speedup vs baseline: 1.1334x; 1.1334x over previous
#include <cuda_runtime.h>
#include <cuda_bf16.h>
#include <cstdint>

#define C_DIM 2048
#define R_DIM 1024
#define B_DIM 16

#define ROWS_PER_BLOCK 16
#define CHUNK_ROWS 2
#define NCHUNKS (ROWS_PER_BLOCK / CHUNK_ROWS)      /* 8 */
#define NBUF 6                                      /* 96KB front-issued, 2 refills */
#define NREFILL (NCHUNKS - NBUF)                    /* 2 */
#define CHUNK_BYTES (CHUNK_ROWS * C_DIM * 4)       /* 16384 */
#define SMEM_TOTAL (NBUF * CHUNK_BYTES + 64)       /* buffers + mbarriers */

// Device-global scratch (no allocations allowed)
__device__ int g_sel_b[C_DIM];   // out col j reads input col g_sel_b[j]
__device__ int g_inv_r[R_DIM];   // input row q goes to output row g_inv_r[q]
__device__ int g_flag[2];        // prep-done flags (col, row); idempotent 0->1

// ---------------- PTX helpers ----------------
__device__ __forceinline__ uint32_t smem_u32(const void* p) {
    return (uint32_t)__cvta_generic_to_shared(p);
}
__device__ __forceinline__ void mbar_init(uint32_t a, uint32_t cnt) {
    asm volatile("mbarrier.init.shared.b64 [%0], %1;" :: "r"(a), "r"(cnt) : "memory");
}
__device__ __forceinline__ void mbar_expect_tx(uint32_t a, uint32_t bytes) {
    asm volatile("mbarrier.arrive.expect_tx.shared.b64 _, [%0], %1;"
                 :: "r"(a), "r"(bytes) : "memory");
}
__device__ __forceinline__ void mbar_wait(uint32_t a, uint32_t parity) {
    asm volatile(
        "{\n\t.reg .pred P;\n\t"
        "WAIT_%=:\n\t"
        "mbarrier.try_wait.parity.acquire.cta.shared::cta.b64 P, [%0], %1, 0x989680;\n\t"
        "@P bra.uni DONE_%=;\n\t"
        "bra.uni WAIT_%=;\n\t"
        "DONE_%=:\n\t}"
        :: "r"(a), "r"(parity) : "memory");
}
__device__ __forceinline__ void bulk_ld(uint32_t dst, const void* src,
                                        uint32_t bytes, uint32_t mbar) {
    asm volatile(
        "cp.async.bulk.shared::cluster.global.mbarrier::complete_tx::bytes [%0], [%1], %2, [%3];"
        :: "r"(dst), "l"(src), "r"(bytes), "r"(mbar) : "memory");
}

// ---------------- block-wide inclusive scan (1024 threads) ----------------
__device__ __forceinline__ void block_scan(int* a, int n, int tid, int* wsum) {
    const int lane = tid & 31, wid = tid >> 5;
    int v0 = 0, v1 = 0;
    const int i0 = 2 * tid;
    if (n == 2048) { v0 = a[i0]; v1 = a[i0 + 1]; }
    else           { v0 = a[tid]; }
    int s = v0 + v1;
    #pragma unroll
    for (int off = 1; off < 32; off <<= 1) {
        int y = __shfl_up_sync(0xffffffffu, s, off);
        if (lane >= off) s += y;
    }
    if (lane == 31) wsum[wid] = s;
    __syncthreads();
    if (wid == 0) {
        int t = wsum[lane];
        #pragma unroll
        for (int off = 1; off < 32; off <<= 1) {
            int y = __shfl_up_sync(0xffffffffu, t, off);
            if (lane >= off) t += y;
        }
        wsum[lane] = t;
    }
    __syncthreads();
    const int excl = (wid ? wsum[wid - 1] : 0) + s - (v0 + v1);
    if (n == 2048) { a[i0] = excl + v0; a[i0 + 1] = excl + v0 + v1; }
    else           { a[tid] = excl + v0; }
    __syncthreads();
}

// ---------------------------------------------------------------------------
// Fused kernel. Blocks 0,1: prep (dedup indices). Blocks 2..: 16 input rows,
// 6-deep front-issued TMA ring; only 2 buffers are reused, so only 2
// __syncthreads (R7's proven refill handshake) — chunks 2..7 consume
// barrier-free with plain full-mbar waits.
// ---------------------------------------------------------------------------
__global__ void __launch_bounds__(1024, 2)
fused_kernel(const float* __restrict__ x, const float* __restrict__ wc,
             const float* __restrict__ wr, float* __restrict__ out)
{
    extern __shared__ char smem[];
    const int tid = threadIdx.x;

    if (blockIdx.x < 2) {
        // ================= PREP =================
        const bool  isC = (blockIdx.x == 0);
        const int   n   = isC ? C_DIM : R_DIM;
        const float* w  = isC ? wc : wr;

        int* sel         = (int*)smem;
        int* firstIdx    = sel + C_DIM;
        int* scanA       = firstIdx + C_DIM;
        int* emptyByRank = scanA + C_DIM;
        __shared__ int wsum[32];
        __shared__ int sh_E;

        const float upper = (float)(n - 1);
        if (n == 2048) {
            const int i0 = 2 * tid;
            sel[i0]     = __float2int_rn(fminf(fmaxf(w[i0],     0.0f), upper));
            sel[i0 + 1] = __float2int_rn(fminf(fmaxf(w[i0 + 1], 0.0f), upper));
            firstIdx[i0] = 0x7fffffff; firstIdx[i0 + 1] = 0x7fffffff;
        } else {
            sel[tid] = __float2int_rn(fminf(fmaxf(w[tid], 0.0f), upper));
            firstIdx[tid] = 0x7fffffff;
        }
        __syncthreads();
        for (int i = tid; i < n; i += 1024) atomicMin(&firstIdx[sel[i]], i);
        __syncthreads();

        // pass 1: scan EMPTY flags over values -> emptyByRank (descending)
        for (int v = tid; v < n; v += 1024)
            scanA[v] = (firstIdx[v] == 0x7fffffff) ? 1 : 0;
        __syncthreads();
        block_scan(scanA, n, tid, wsum);
        if (tid == 0) sh_E = scanA[n - 1];
        __syncthreads();
        const int E = sh_E;
        for (int v = tid; v < n; v += 1024) {
            if (firstIdx[v] == 0x7fffffff) {
                int asc = scanA[v] - 1;
                emptyByRank[E - 1 - asc] = v;   // slot 0 = largest empty value
            }
        }
        __syncthreads();

        // pass 2: scan DUP flags over indices -> duplicate rank
        for (int i = tid; i < n; i += 1024)
            scanA[i] = (firstIdx[sel[i]] != i) ? 1 : 0;
        __syncthreads();
        block_scan(scanA, n, tid, wsum);

        for (int i = tid; i < n; i += 1024) {
            bool dup = (firstIdx[sel[i]] != i);
            int v = dup ? emptyByRank[scanA[i] - 1] : sel[i];
            if (isC) g_sel_b[i] = v;     // column gather index
            else     g_inv_r[v] = i;     // inverse row permutation (v is a perm)
        }
        __threadfence();
        __syncthreads();
        if (tid == 0) {
            int* f = &g_flag[isC ? 0 : 1];
            asm volatile("st.release.gpu.global.b32 [%0], %1;"
                         :: "l"(f), "r"(1) : "memory");
        }
        return;
    }

    // ================= GATHER / SCATTER =================
    const int q0 = (int)(blockIdx.x - 2) * ROWS_PER_BLOCK;   // first input row
    const uint32_t sbase = smem_u32(smem);
    const uint32_t mbarb = sbase + NBUF * CHUNK_BYTES;

    if (tid == 0) {
        #pragma unroll
        for (int p = 0; p < NBUF; p++) mbar_init(mbarb + 8 * p, 1);
        asm volatile("fence.proxy.async.shared::cta;" ::: "memory");
        // Prologue: 6 chunks (96KB) issued immediately.
        #pragma unroll
        for (int p = 0; p < NBUF; p++) {
            mbar_expect_tx(mbarb + 8 * p, CHUNK_BYTES);
            bulk_ld(sbase + p * CHUNK_BYTES,
                    x + (size_t)(q0 + p * CHUNK_ROWS) * C_DIM,
                    CHUNK_BYTES, mbarb + 8 * p);
        }
        // Wait for prep (overlapped with the loads above).
        int a, b;
        do {
            asm volatile("ld.acquire.gpu.global.b32 %0, [%1];" : "=r"(a) : "l"(&g_flag[0]));
            asm volatile("ld.acquire.gpu.global.b32 %0, [%1];" : "=r"(b) : "l"(&g_flag[1]));
        } while (!(a && b));
    }
    __syncthreads();   // barriers initialized + prep visible to all

    // Fixed per-thread slot: row k within chunk (0/1), float4 column c4.
    const int c4 = tid & 511;
    const int k  = tid >> 9;
    const int4 bj = ((const int4*)g_sel_b)[c4];    // reused across all chunks

    #pragma unroll
    for (int c = 0; c < NCHUNKS; c++) {
        const int b = (c < NBUF) ? c : c - NBUF;          // buffer index
        const uint32_t full_mb = mbarb + 8 * b;

        mbar_wait(full_mb, (c < NBUF) ? 0 : 1);
        const float* srow = (const float*)(smem + b * CHUNK_BYTES) + k * C_DIM;

        const int Q = q0 + c * CHUNK_ROWS + k;               // input row (flat)
        const int orow = (Q & ~(R_DIM - 1)) | g_inv_r[Q & (R_DIM - 1)];
        float4 v;
        v.x = srow[bj.x]; v.y = srow[bj.y]; v.z = srow[bj.z]; v.w = srow[bj.w];
        __stwt(((float4*)out) + (size_t)orow * (C_DIM / 4) + c4, v);

        if (c < NREFILL) {
            __syncthreads();             // buffer b fully consumed (R7 handshake)
            if (tid == 0) {
                mbar_expect_tx(full_mb, CHUNK_BYTES);
                bulk_ld(sbase + b * CHUNK_BYTES,
                        x + (size_t)(q0 + (c + NBUF) * CHUNK_ROWS) * C_DIM,
                        CHUNK_BYTES, full_mb);
            }
        }
    }
}

extern "C" void kernel_launch(void* const* d_in, const int* in_sizes, int n_in,
                              void* d_out, int out_size) {
    const float* x  = (const float*)d_in[0];   // [16, 1024, 2048] f32
    const float* wc = (const float*)d_in[1];   // [2048] f32
    const float* wr = (const float*)d_in[2];   // [1024] f32
    float* out = (float*)d_out;

    cudaFuncSetAttribute(fused_kernel,
                         cudaFuncAttributeMaxDynamicSharedMemorySize, SMEM_TOTAL);
    const int grid = 2 + (B_DIM * R_DIM) / ROWS_PER_BLOCK;   // 1026
    fused_kernel<<<grid, 1024, SMEM_TOTAL>>>(x, wc, wr, out);
}

// round 16
// speedup vs baseline: 1.1342x; 1.0007x over previous
#include <cuda_runtime.h>
#include <cuda_bf16.h>
#include <cstdint>

#define C_DIM 2048
#define R_DIM 1024
#define B_DIM 16

#define ROWS_PER_BLOCK 16
#define CHUNK_ROWS 4
#define NCHUNKS (ROWS_PER_BLOCK / CHUNK_ROWS)      /* 4 */
#define NBUF 3                                      /* 96KB front-issued */
#define NREFILL (NCHUNKS - NBUF)                    /* 1 */
#define CHUNK_BYTES (CHUNK_ROWS * C_DIM * 4)       /* 32768 */
#define SMEM_TOTAL (NBUF * CHUNK_BYTES + 64)       /* buffers + mbarriers */

// Device-global scratch (no allocations allowed)
__device__ int g_sel_b[C_DIM];   // out col j reads input col g_sel_b[j]
__device__ int g_inv_r[R_DIM];   // input row q goes to output row g_inv_r[q]
__device__ int g_flag[2];        // prep-done flags (col, row); idempotent 0->1

// ---------------- PTX helpers ----------------
__device__ __forceinline__ uint32_t smem_u32(const void* p) {
    return (uint32_t)__cvta_generic_to_shared(p);
}
__device__ __forceinline__ void mbar_init(uint32_t a, uint32_t cnt) {
    asm volatile("mbarrier.init.shared.b64 [%0], %1;" :: "r"(a), "r"(cnt) : "memory");
}
__device__ __forceinline__ void mbar_expect_tx(uint32_t a, uint32_t bytes) {
    asm volatile("mbarrier.arrive.expect_tx.shared.b64 _, [%0], %1;"
                 :: "r"(a), "r"(bytes) : "memory");
}
__device__ __forceinline__ void mbar_wait(uint32_t a, uint32_t parity) {
    asm volatile(
        "{\n\t.reg .pred P;\n\t"
        "WAIT_%=:\n\t"
        "mbarrier.try_wait.parity.acquire.cta.shared::cta.b64 P, [%0], %1, 0x989680;\n\t"
        "@P bra.uni DONE_%=;\n\t"
        "bra.uni WAIT_%=;\n\t"
        "DONE_%=:\n\t}"
        :: "r"(a), "r"(parity) : "memory");
}
__device__ __forceinline__ void bulk_ld(uint32_t dst, const void* src,
                                        uint32_t bytes, uint32_t mbar) {
    asm volatile(
        "cp.async.bulk.shared::cluster.global.mbarrier::complete_tx::bytes [%0], [%1], %2, [%3];"
        :: "r"(dst), "l"(src), "r"(bytes), "r"(mbar) : "memory");
}

// ---------------- block-wide inclusive scan (1024 threads) ----------------
__device__ __forceinline__ void block_scan(int* a, int n, int tid, int* wsum) {
    const int lane = tid & 31, wid = tid >> 5;
    int v0 = 0, v1 = 0;
    const int i0 = 2 * tid;
    if (n == 2048) { v0 = a[i0]; v1 = a[i0 + 1]; }
    else           { v0 = a[tid]; }
    int s = v0 + v1;
    #pragma unroll
    for (int off = 1; off < 32; off <<= 1) {
        int y = __shfl_up_sync(0xffffffffu, s, off);
        if (lane >= off) s += y;
    }
    if (lane == 31) wsum[wid] = s;
    __syncthreads();
    if (wid == 0) {
        int t = wsum[lane];
        #pragma unroll
        for (int off = 1; off < 32; off <<= 1) {
            int y = __shfl_up_sync(0xffffffffu, t, off);
            if (lane >= off) t += y;
        }
        wsum[lane] = t;
    }
    __syncthreads();
    const int excl = (wid ? wsum[wid - 1] : 0) + s - (v0 + v1);
    if (n == 2048) { a[i0] = excl + v0; a[i0 + 1] = excl + v0 + v1; }
    else           { a[tid] = excl + v0; }
    __syncthreads();
}

// ---------------------------------------------------------------------------
// Fused kernel. Blocks 0,1: prep (dedup indices). Blocks 2..: 16 input rows,
// 3 x 32KB TMA buffers front-issued, one refill (one __syncthreads total).
// Consume: per chunk each thread gathers+stores 2 independent rows (ILP=2).
// ---------------------------------------------------------------------------
__global__ void __launch_bounds__(1024, 2)
fused_kernel(const float* __restrict__ x, const float* __restrict__ wc,
             const float* __restrict__ wr, float* __restrict__ out)
{
    extern __shared__ char smem[];
    const int tid = threadIdx.x;

    if (blockIdx.x < 2) {
        // ================= PREP =================
        const bool  isC = (blockIdx.x == 0);
        const int   n   = isC ? C_DIM : R_DIM;
        const float* w  = isC ? wc : wr;

        int* sel         = (int*)smem;
        int* firstIdx    = sel + C_DIM;
        int* scanA       = firstIdx + C_DIM;
        int* emptyByRank = scanA + C_DIM;
        __shared__ int wsum[32];
        __shared__ int sh_E;

        const float upper = (float)(n - 1);
        if (n == 2048) {
            const int i0 = 2 * tid;
            sel[i0]     = __float2int_rn(fminf(fmaxf(w[i0],     0.0f), upper));
            sel[i0 + 1] = __float2int_rn(fminf(fmaxf(w[i0 + 1], 0.0f), upper));
            firstIdx[i0] = 0x7fffffff; firstIdx[i0 + 1] = 0x7fffffff;
        } else {
            sel[tid] = __float2int_rn(fminf(fmaxf(w[tid], 0.0f), upper));
            firstIdx[tid] = 0x7fffffff;
        }
        __syncthreads();
        for (int i = tid; i < n; i += 1024) atomicMin(&firstIdx[sel[i]], i);
        __syncthreads();

        // pass 1: scan EMPTY flags over values -> emptyByRank (descending)
        for (int v = tid; v < n; v += 1024)
            scanA[v] = (firstIdx[v] == 0x7fffffff) ? 1 : 0;
        __syncthreads();
        block_scan(scanA, n, tid, wsum);
        if (tid == 0) sh_E = scanA[n - 1];
        __syncthreads();
        const int E = sh_E;
        for (int v = tid; v < n; v += 1024) {
            if (firstIdx[v] == 0x7fffffff) {
                int asc = scanA[v] - 1;
                emptyByRank[E - 1 - asc] = v;   // slot 0 = largest empty value
            }
        }
        __syncthreads();

        // pass 2: scan DUP flags over indices -> duplicate rank
        for (int i = tid; i < n; i += 1024)
            scanA[i] = (firstIdx[sel[i]] != i) ? 1 : 0;
        __syncthreads();
        block_scan(scanA, n, tid, wsum);

        for (int i = tid; i < n; i += 1024) {
            bool dup = (firstIdx[sel[i]] != i);
            int v = dup ? emptyByRank[scanA[i] - 1] : sel[i];
            if (isC) g_sel_b[i] = v;     // column gather index
            else     g_inv_r[v] = i;     // inverse row permutation (v is a perm)
        }
        __threadfence();
        __syncthreads();
        if (tid == 0) {
            int* f = &g_flag[isC ? 0 : 1];
            asm volatile("st.release.gpu.global.b32 [%0], %1;"
                         :: "l"(f), "r"(1) : "memory");
        }
        return;
    }

    // ================= GATHER / SCATTER =================
    const int q0 = (int)(blockIdx.x - 2) * ROWS_PER_BLOCK;   // first input row
    const uint32_t sbase = smem_u32(smem);
    const uint32_t mbarb = sbase + NBUF * CHUNK_BYTES;

    if (tid == 0) {
        #pragma unroll
        for (int p = 0; p < NBUF; p++) mbar_init(mbarb + 8 * p, 1);
        asm volatile("fence.proxy.async.shared::cta;" ::: "memory");
        // Prologue: 3 x 32KB chunks issued immediately (96KB in flight).
        #pragma unroll
        for (int p = 0; p < NBUF; p++) {
            mbar_expect_tx(mbarb + 8 * p, CHUNK_BYTES);
            bulk_ld(sbase + p * CHUNK_BYTES,
                    x + (size_t)(q0 + p * CHUNK_ROWS) * C_DIM,
                    CHUNK_BYTES, mbarb + 8 * p);
        }
        // Wait for prep (overlapped with the loads above).
        int a, b;
        do {
            asm volatile("ld.acquire.gpu.global.b32 %0, [%1];" : "=r"(a) : "l"(&g_flag[0]));
            asm volatile("ld.acquire.gpu.global.b32 %0, [%1];" : "=r"(b) : "l"(&g_flag[1]));
        } while (!(a && b));
    }
    __syncthreads();   // barriers initialized + prep visible to all

    // Fixed per-thread slots: float4 column c4, rows k0 and k0+2 per chunk.
    const int c4 = tid & 511;
    const int k0 = tid >> 9;                       // 0 or 1
    const int4 bj = ((const int4*)g_sel_b)[c4];    // reused across all chunks

    #pragma unroll
    for (int c = 0; c < NCHUNKS; c++) {
        const int b = (c < NBUF) ? c : c - NBUF;          // buffer index
        const uint32_t full_mb = mbarb + 8 * b;

        mbar_wait(full_mb, (c < NBUF) ? 0 : 1);
        const float* buf = (const float*)(smem + b * CHUNK_BYTES);

        // Two independent rows per thread -> gather/store ILP.
        const int Qa = q0 + c * CHUNK_ROWS + k0;
        const int Qb = Qa + 2;
        const int orowA = (Qa & ~(R_DIM - 1)) | g_inv_r[Qa & (R_DIM - 1)];
        const int orowB = (Qb & ~(R_DIM - 1)) | g_inv_r[Qb & (R_DIM - 1)];
        const float* sA = buf + k0 * C_DIM;
        const float* sB = buf + (k0 + 2) * C_DIM;
        float4 va, vb;
        va.x = sA[bj.x]; va.y = sA[bj.y]; va.z = sA[bj.z]; va.w = sA[bj.w];
        vb.x = sB[bj.x]; vb.y = sB[bj.y]; vb.z = sB[bj.z]; vb.w = sB[bj.w];
        __stwt(((float4*)out) + (size_t)orowA * (C_DIM / 4) + c4, va);
        __stwt(((float4*)out) + (size_t)orowB * (C_DIM / 4) + c4, vb);

        if (c < NREFILL) {
            __syncthreads();             // buffer b fully consumed
            if (tid == 0) {
                mbar_expect_tx(full_mb, CHUNK_BYTES);
                bulk_ld(sbase + b * CHUNK_BYTES,
                        x + (size_t)(q0 + (c + NBUF) * CHUNK_ROWS) * C_DIM,
                        CHUNK_BYTES, full_mb);
            }
        }
    }
}

extern "C" void kernel_launch(void* const* d_in, const int* in_sizes, int n_in,
                              void* d_out, int out_size) {
    const float* x  = (const float*)d_in[0];   // [16, 1024, 2048] f32
    const float* wc = (const float*)d_in[1];   // [2048] f32
    const float* wr = (const float*)d_in[2];   // [1024] f32
    float* out = (float*)d_out;

    cudaFuncSetAttribute(fused_kernel,
                         cudaFuncAttributeMaxDynamicSharedMemorySize, SMEM_TOTAL);
    const int grid = 2 + (B_DIM * R_DIM) / ROWS_PER_BLOCK;   // 1026
    fused_kernel<<<grid, 1024, SMEM_TOTAL>>>(x, wc, wr, out);
}